// round 9
// baseline (speedup 1.0000x reference)
#include <cuda_runtime.h>
#include <cuda_fp16.h>
#include <cstdint>

// Problem constants
#define N_B   4
#define C_IN  256
#define H_IM  64
#define W_IM  64
#define OC    256
#define K2    9
#define OMC   27
#define HW    (H_IM*W_IM)        // 4096
#define NPIX  (N_B*HW)           // 16384
#define KDIM  (C_IN*K2)          // 2304
#define NCHK  (KDIM/32)          // 72
#define NTILE (NPIX/128)         // 128

// ---------------- device scratch ----------------
__device__ float  g_om  [(size_t)N_B * OMC * HW];
__device__ float  g_xt  [(size_t)NPIX * C_IN];          // x transposed: [n][hw][c]
__device__ __half g_colA[(size_t)NTILE * NCHK * 4096];  // tiled im2col, swizzled
__device__ __half g_wtB [(size_t)NCHK * 8192];          // dcn weights, pre-swizzled
__device__ __half g_owB [(size_t)NCHK * 1024];          // offset weights, pre-swizzled

__device__ __host__ __forceinline__ uint32_t swz64(uint32_t a) {
    return a ^ (((a >> 7) & 3u) << 4);
}
__device__ __host__ __forceinline__ uint32_t swzA(uint32_t a) {
    return a ^ (((a >> 8) & 7u) << 4);
}

__device__ __forceinline__ void sts16(uint32_t addr, unsigned short v) {
    asm volatile("st.shared.u16 [%0], %1;" :: "r"(addr), "h"(v));
}
__device__ __forceinline__ uint32_t lds32(uint32_t addr) {
    uint32_t v;
    asm volatile("ld.shared.b32 %0, [%1];" : "=r"(v) : "r"(addr));
    return v;
}
__device__ __forceinline__ void ldmx4(uint32_t* r, uint32_t addr) {
    asm volatile("ldmatrix.sync.aligned.m8n8.x4.shared.b16 {%0,%1,%2,%3}, [%4];"
        : "=r"(r[0]), "=r"(r[1]), "=r"(r[2]), "=r"(r[3]) : "r"(addr));
}
__device__ __forceinline__ void ldmx4t(uint32_t* r, uint32_t addr) {
    asm volatile("ldmatrix.sync.aligned.m8n8.x4.trans.shared.b16 {%0,%1,%2,%3}, [%4];"
        : "=r"(r[0]), "=r"(r[1]), "=r"(r[2]), "=r"(r[3]) : "r"(addr));
}
__device__ __forceinline__ void mma_f16(float* c, const uint32_t* a, const uint32_t* b) {
    asm volatile(
        "mma.sync.aligned.m16n8k16.row.col.f32.f16.f16.f32 "
        "{%0,%1,%2,%3}, {%4,%5,%6,%7}, {%8,%9}, {%0,%1,%2,%3};"
        : "+f"(c[0]), "+f"(c[1]), "+f"(c[2]), "+f"(c[3])
        : "r"(a[0]), "r"(a[1]), "r"(a[2]), "r"(a[3]), "r"(b[0]), "r"(b[1]));
}

// ---------------------------------------------------------------------------
// Prep: pack both weight tensors (fp16, chunk-major, pre-swizzled).
// ---------------------------------------------------------------------------
__global__ void prep_kernel(const float* __restrict__ dw,
                            const float* __restrict__ ow)
{
    if (blockIdx.x < 256) {
        int oc = blockIdx.x;
        int c  = threadIdx.x;
        #pragma unroll
        for (int k = 0; k < 9; k++) {
            float w = dw[((size_t)oc * C_IN + c) * K2 + k];
            int ch  = k * 8 + (c >> 5);
            int kcl = c & 31;
            uint32_t raw = (uint32_t)oc * 64 + kcl * 2;
            g_wtB[(size_t)ch * 8192 + (swz64(raw) >> 1)] = __float2half_rn(w);
        }
    } else {
        int ch = blockIdx.x - 256;
        int k  = ch >> 3;
        int c0 = (ch & 7) * 32;
        #pragma unroll
        for (int it = 0; it < 4; it++) {
            int idx = threadIdx.x + it * 256;
            int oc = idx >> 5, kcl = idx & 31;
            float w = (oc < OMC)
                ? ow[((size_t)oc * C_IN + c0 + kcl) * K2 + k] : 0.f;
            uint32_t raw = (uint32_t)oc * 64 + kcl * 2;
            g_owB[(size_t)ch * 1024 + (swz64(raw) >> 1)] = __float2half_rn(w);
        }
    }
}

// ---------------------------------------------------------------------------
// Transpose x [n][c][hw] -> g_xt [n][hw][c].  grid (64 hw-tiles, 4 c-tiles, 4 n)
// ---------------------------------------------------------------------------
__global__ void transpose_x_kernel(const float* __restrict__ x)
{
    __shared__ float ts[64][65];
    const int hw0 = blockIdx.x * 64, c0 = blockIdx.y * 64, n = blockIdx.z;
    const float* xn = x + ((size_t)(n * C_IN + c0) << 12) + hw0;
    for (int i = threadIdx.x; i < 64 * 64; i += 256) {
        int r = i >> 6, col = i & 63;         // r = c, col = hw
        ts[r][col] = xn[((size_t)r << 12) + col];
    }
    __syncthreads();
    float* xtn = g_xt + (((size_t)n << 12) + hw0) * C_IN + c0;
    for (int i = threadIdx.x; i < 64 * 64; i += 256) {
        int r = i >> 6, col = i & 63;         // r = hw, col = c
        xtn[(size_t)r * C_IN + col] = ts[col][r];
    }
}

// ---------------------------------------------------------------------------
// Offset conv as fp16 implicit GEMM (unchanged from R8)
// ---------------------------------------------------------------------------
#define CV_APITCH 272
#define CV_A_SZ   (32 * CV_APITCH)
#define CV_B_SZ   2048
#define CV_STG    (CV_A_SZ + CV_B_SZ)

__global__ void __launch_bounds__(256, 1) conv_gemm_kernel(
    const float* __restrict__ x, const float* __restrict__ ob)
{
    __shared__ char sm[2 * CV_STG];
    const uint32_t sb = (uint32_t)__cvta_generic_to_shared(sm);
    const int tid = threadIdx.x;
    const int wid = tid >> 5, lid = tid & 31;
    const int bm0 = blockIdx.x * 128;
    const int nIdx = bm0 >> 12, hwb = bm0 & 4095, ho0 = hwb >> 6;
    const float* xn = x + ((size_t)nIdx * C_IN << 12);

    const int p = tid & 127;
    const int kcl0 = tid >> 7;
    const int pho = p >> 6, pwo = p & 63;

    float acc[4][4];
    #pragma unroll
    for (int j = 0; j < 4; j++)
        #pragma unroll
        for (int q = 0; q < 4; q++) acc[j][q] = 0.f;

    auto build = [&](int ch, int st) {
        const int k = ch >> 3, c0 = (ch & 7) * 32;
        const int dy = k / 3 - 1, dx = k % 3 - 1;
        const int hy = ho0 + pho + dy;
        const int wx = pwo + dx;
        const bool v = ((unsigned)hy < 64u) && ((unsigned)wx < 64u);
        const float* src = xn + ((size_t)(c0 + kcl0) << 12) + (hy << 6) + wx;
        const uint32_t dst = sb + st * CV_STG + kcl0 * CV_APITCH + p * 2;
        #pragma unroll
        for (int it = 0; it < 16; it++) {
            float val = 0.f;
            if (v) val = src[(size_t)(it * 2) << 12];
            sts16(dst + it * 2 * CV_APITCH,
                  __half_as_ushort(__float2half_rn(val)));
        }
        if (tid < 128) {
            const uint4* bsrc = (const uint4*)(g_owB + (size_t)ch * 1024);
            *(uint4*)(sm + st * CV_STG + CV_A_SZ + tid * 16) = bsrc[tid];
        }
    };

    const int qq = lid >> 3, jr = lid & 7;
    const uint32_t aoff = (uint32_t)(((qq >> 1) * 8 + jr) * CV_APITCH
                                     + (wid * 16 + (qq & 1) * 8) * 2);
    const int oc_l = (qq >> 1) * 8 + jr;

    build(0, 0);
    __syncthreads();

    for (int ch = 0; ch < NCHK; ch++) {
        const int st = ch & 1;
        if (ch + 1 < NCHK) build(ch + 1, st ^ 1);

        const uint32_t ab = sb + st * CV_STG;
        const uint32_t bb = ab + CV_A_SZ;
        #pragma unroll
        for (int kp = 0; kp < 2; kp++) {
            uint32_t Af[4];
            ldmx4t(Af, ab + aoff + kp * (16 * CV_APITCH));
            #pragma unroll
            for (int pi = 0; pi < 2; pi++) {
                uint32_t Bf[4];
                uint32_t raw = (uint32_t)(oc_l + pi * 16) * 64
                             + (kp * 2 + (qq & 1)) * 16;
                ldmx4(Bf, bb + swz64(raw));
                mma_f16(acc[pi*2],   Af, &Bf[0]);
                mma_f16(acc[pi*2+1], Af, &Bf[2]);
            }
        }
        __syncthreads();
    }

    float* T = (float*)sm;
    const int r0 = wid * 16 + (lid >> 2);
    #pragma unroll
    for (int jj = 0; jj < 4; jj++) {
        int oc = jj * 8 + (lid & 3) * 2;
        T[ oc      * 136 + r0    ] = acc[jj][0];
        T[(oc + 1) * 136 + r0    ] = acc[jj][1];
        T[ oc      * 136 + r0 + 8] = acc[jj][2];
        T[(oc + 1) * 136 + r0 + 8] = acc[jj][3];
    }
    __syncthreads();
    for (int idx = tid; idx < OMC * 128; idx += 256) {
        int o = idx >> 7, m = idx & 127;
        g_om[((size_t)(nIdx * OMC + o) << 12) + hwb + m] = T[o * 136 + m] + ob[o];
    }
}

// ---------------------------------------------------------------------------
// Sampling v2: channel-major gathers from g_xt, per-warp smem transpose,
// coalesced swizzled stores to g_colA. grid = 128 tiles, 512 threads.
// ---------------------------------------------------------------------------
#define S2_SW    0                      // 1152 * 16 = 18432
#define S2_SI    18432                  // 1152 * 16 = 18432
#define S2_STGB  36864                  // 16 warps * 4224
#define S2_WSTG  4224                   // [32 ch][66 halfs] pitch 132B
#define S2_SMEM  (S2_STGB + 16 * S2_WSTG)   // 104448

__global__ void __launch_bounds__(512, 1) sample2_kernel()
{
    extern __shared__ char sm2[];
    float4* sW = (float4*)(sm2 + S2_SW);
    int4*   sI = (int4*)(sm2 + S2_SI);
    const uint32_t sb = (uint32_t)__cvta_generic_to_shared(sm2);

    const int tile = blockIdx.x;
    const int n    = tile >> 5;
    const int hw0  = (tile & 31) * 128;

    // ---- phase 1: bilinear weights + channel-major corner offsets ----
    const float* omn = g_om + (size_t)n * OMC * HW;
    for (int t = threadIdx.x; t < 9 * 128; t += 512) {
        int k = t >> 7, pl = t & 127;
        int p = hw0 + pl;
        int ho = p >> 6, wo = p & 63;

        float oy = omn[((size_t)(2*k    ) << 12) + p];
        float ox = omn[((size_t)(2*k + 1) << 12) + p];
        float mv = omn[((size_t)(18 + k ) << 12) + p];
        float m  = 1.0f / (1.0f + expf(-mv));

        float him = (float)(ho + (k / 3) - 1) + oy;
        float wim = (float)(wo + (k % 3) - 1) + ox;

        float y0 = floorf(him), x0 = floorf(wim);
        float lh = him - y0,    lw = wim - x0;
        float hh = 1.0f - lh,   hw = 1.0f - lw;
        float y1 = y0 + 1.0f,   x1 = x0 + 1.0f;

        float vy0 = (y0 >= 0.f && y0 <= 63.f) ? 1.f : 0.f;
        float vy1 = (y1 >= 0.f && y1 <= 63.f) ? 1.f : 0.f;
        float vx0 = (x0 >= 0.f && x0 <= 63.f) ? 1.f : 0.f;
        float vx1 = (x1 >= 0.f && x1 <= 63.f) ? 1.f : 0.f;

        int iy0 = (int)fminf(fmaxf(y0, 0.f), 63.f);
        int iy1 = (int)fminf(fmaxf(y1, 0.f), 63.f);
        int ix0 = (int)fminf(fmaxf(x0, 0.f), 63.f);
        int ix1 = (int)fminf(fmaxf(x1, 0.f), 63.f);

        sW[t] = make_float4(hh*hw*m*vy0*vx0, hh*lw*m*vy0*vx1,
                            lh*hw*m*vy1*vx0, lh*lw*m*vy1*vx1);
        sI[t] = make_int4((iy0*64 + ix0) << 8, (iy0*64 + ix1) << 8,
                          (iy1*64 + ix0) << 8, (iy1*64 + ix1) << 8);
    }
    __syncthreads();

    // ---- phase 2: 144 warp-tasks (9 taps x 8 ch-groups x 2 px-halves) ----
    const int wid = threadIdx.x >> 5, lid = threadIdx.x & 31;
    const float* xtn = g_xt + (((size_t)n << 12)) * C_IN;
    char* tbase = (char*)g_colA + (size_t)tile * NCHK * 8192;
    const uint32_t stgb = sb + S2_STGB + wid * S2_WSTG;

    #pragma unroll 1
    for (int i = 0; i < 9; i++) {
        int tt = wid + 16 * i;
        int k = tt >> 4, g = (tt & 15) >> 1, pb = tt & 1;
        const float* xc = xtn + g * 32 + lid;

        #pragma unroll 4
        for (int j = 0; j < 64; j++) {
            int t = (k << 7) + (pb << 6) + j;
            float4 w = sW[t];
            int4   I = sI[t];
            float v = w.x * xc[I.x] + w.y * xc[I.y]
                    + w.z * xc[I.z] + w.w * xc[I.w];
            sts16(stgb + lid * 132 + j * 2,
                  __half_as_ushort(__float2half_rn(v)));
        }
        __syncwarp();

        char* cb = tbase + (size_t)(k * 8 + g) * 8192;
        #pragma unroll
        for (int kcl = 0; kcl < 32; kcl++) {
            uint32_t v = lds32(stgb + kcl * 132 + lid * 4);
            *(uint32_t*)(cb + swzA((uint32_t)(kcl * 256 + pb * 128 + lid * 4))) = v;
        }
        __syncwarp();
    }
}

// ---------------------------------------------------------------------------
// fp16 mma GEMM: contiguous bulk staging, 4 stages (unchanged from R8)
// ---------------------------------------------------------------------------
#define A_TILE   8192
#define B_TILE   16384
#define STAGE_SZ (A_TILE + B_TILE)
#define NSTAGE   4
#define MBAR_OFF (NSTAGE * STAGE_SZ)
#define GEMM_SMEM (MBAR_OFF + 128)
#define STAGE_BYTES STAGE_SZ

__device__ __forceinline__ void bulk_g2s(uint32_t dst, const void* src,
                                         uint32_t bytes, uint32_t mbar) {
    asm volatile(
        "cp.async.bulk.shared::cluster.global.mbarrier::complete_tx::bytes "
        "[%0], [%1], %2, [%3];"
        :: "r"(dst), "l"(src), "r"(bytes), "r"(mbar) : "memory");
}
__device__ __forceinline__ void mbar_init(uint32_t a, uint32_t c) {
    asm volatile("mbarrier.init.shared.b64 [%0], %1;" :: "r"(a), "r"(c) : "memory");
}
__device__ __forceinline__ void mbar_expect(uint32_t a, uint32_t b) {
    asm volatile("mbarrier.arrive.expect_tx.shared.b64 _, [%0], %1;" :: "r"(a), "r"(b) : "memory");
}
__device__ __forceinline__ void mbar_arrive(uint32_t a) {
    asm volatile("mbarrier.arrive.shared.b64 _, [%0];" :: "r"(a) : "memory");
}
__device__ __forceinline__ void mbar_wait(uint32_t mbar, uint32_t parity) {
    uint32_t done;
    asm volatile("{\n\t.reg .pred p;\n\t"
        "mbarrier.try_wait.parity.acquire.cta.shared::cta.b64 p, [%1], %2;\n\t"
        "selp.b32 %0, 1, 0, p;\n\t}"
        : "=r"(done) : "r"(mbar), "r"(parity) : "memory");
    if (!done) {
        asm volatile("{\n\t.reg .pred P1;\n\t"
            "W_%=:\n\t"
            "mbarrier.try_wait.parity.acquire.cta.shared::cta.b64 P1, [%0], %1, 0x989680;\n\t"
            "@P1 bra.uni D_%=;\n\t"
            "bra.uni W_%=;\n\t"
            "D_%=:\n\t}" :: "r"(mbar), "r"(parity) : "memory");
    }
}

__global__ void __launch_bounds__(512, 1) gemm_bulk_kernel(float* __restrict__ out)
{
    extern __shared__ char sm[];
    const uint32_t sb = (uint32_t)__cvta_generic_to_shared(sm);
    const int tid = threadIdx.x;
    const int wid = tid >> 5, lid = tid & 31;
    const int warpM = wid & 3, warpN = wid >> 2;
    const int bm0 = blockIdx.x * 128;
    const int tile = blockIdx.x;

    if (tid == 0) {
        #pragma unroll
        for (int s = 0; s < NSTAGE; s++) {
            mbar_init(sb + MBAR_OFF + s*16, 1);
            mbar_init(sb + MBAR_OFF + s*16 + 8, 512);
        }
    }
    __syncthreads();

    float acc[2][8][4];
    #pragma unroll
    for (int i = 0; i < 2; i++)
        #pragma unroll
        for (int j = 0; j < 8; j++)
            #pragma unroll
            for (int q = 0; q < 4; q++) acc[i][j][q] = 0.f;

    const char* aSrc = (const char*)g_colA + (size_t)tile * NCHK * 8192;

    auto fill = [&](int f) {
        int s = f % NSTAGE;
        uint32_t base = sb + s * STAGE_SZ;
        uint32_t mb   = sb + MBAR_OFF + s * 16;
        mbar_expect(mb, STAGE_BYTES);
        bulk_g2s(base, aSrc + (size_t)f * 8192, A_TILE, mb);
        bulk_g2s(base + A_TILE, g_wtB + (size_t)f * 8192, B_TILE, mb);
    };

    if (tid == 0) {
        #pragma unroll
        for (int f = 0; f < NSTAGE - 1; f++) fill(f);
    }

    const int qq = lid >> 3;
    const int jr = lid & 7;
    const uint32_t aoff = (uint32_t)(((qq >> 1) * 8 + jr) * 256
                                     + (warpM * 32 + (qq & 1) * 8) * 2);
    const int oc_lane = warpN * 64 + (qq >> 1) * 8 + jr;

    for (int ch = 0; ch < NCHK; ch++) {
        if (tid == 0) {
            int f = ch + NSTAGE - 1;
            if (f < NCHK) {
                if (f >= NSTAGE)
                    mbar_wait(sb + MBAR_OFF + (f % NSTAGE) * 16 + 8,
                              ((f / NSTAGE) - 1) & 1);
                fill(f);
            }
        }
        const int s = ch % NSTAGE;
        mbar_wait(sb + MBAR_OFF + s * 16, (ch / NSTAGE) & 1);

        const uint32_t ab = sb + s * STAGE_SZ;
        const uint32_t bb = ab + A_TILE;

        #pragma unroll
        for (int kp = 0; kp < 2; kp++) {
            uint32_t Af[2][4], Bf[4][4];
            #pragma unroll
            for (int mi = 0; mi < 2; mi++)
                ldmx4t(Af[mi], ab + swzA(aoff + kp * (16 * 256) + mi * 32));
            #pragma unroll
            for (int pi = 0; pi < 4; pi++) {
                uint32_t raw = (uint32_t)(oc_lane + pi * 16) * 64
                             + (kp * 2 + (qq & 1)) * 16;
                ldmx4(Bf[pi], bb + swz64(raw));
            }
            #pragma unroll
            for (int mi = 0; mi < 2; mi++)
                #pragma unroll
                for (int pi = 0; pi < 4; pi++) {
                    mma_f16(acc[mi][pi*2],   Af[mi], &Bf[pi][0]);
                    mma_f16(acc[mi][pi*2+1], Af[mi], &Bf[pi][2]);
                }
        }
        mbar_arrive(sb + MBAR_OFF + s * 16 + 8);
    }

    const int nIdx = bm0 >> 12;
    const int hwb  = bm0 & 4095;
    #pragma unroll
    for (int mi = 0; mi < 2; mi++) {
        int r = hwb + warpM * 32 + mi * 16 + (lid >> 2);
        #pragma unroll
        for (int jj = 0; jj < 8; jj++) {
            int oc = warpN * 64 + jj * 8 + (lid & 3) * 2;
            size_t base = ((size_t)(nIdx * OC + oc) << 12);
            out[base + r]            = acc[mi][jj][0];
            out[base + 4096 + r]     = acc[mi][jj][1];
            out[base + r + 8]        = acc[mi][jj][2];
            out[base + 4096 + r + 8] = acc[mi][jj][3];
        }
    }
}

// ---------------------------------------------------------------------------
extern "C" void kernel_launch(void* const* d_in, const int* in_sizes, int n_in,
                              void* d_out, int out_size)
{
    const float* x  = (const float*)d_in[0];
    const float* ow = (const float*)d_in[1];
    const float* ob = (const float*)d_in[2];
    const float* dw = (const float*)d_in[3];
    float* out = (float*)d_out;

    cudaFuncSetAttribute(gemm_bulk_kernel,
        cudaFuncAttributeMaxDynamicSharedMemorySize, GEMM_SMEM);
    cudaFuncSetAttribute(sample2_kernel,
        cudaFuncAttributeMaxDynamicSharedMemorySize, S2_SMEM);

    prep_kernel<<<256 + NCHK, 256>>>(dw, ow);
    transpose_x_kernel<<<dim3(64, 4, 4), 256>>>(x);
    conv_gemm_kernel<<<NPIX/128, 256>>>(x, ob);
    sample2_kernel<<<NTILE, 512, S2_SMEM>>>();
    gemm_bulk_kernel<<<NPIX/128, 512, GEMM_SMEM>>>(out);
}

// round 10
// speedup vs baseline: 1.2670x; 1.2670x over previous
#include <cuda_runtime.h>
#include <cuda_fp16.h>
#include <cstdint>

// Problem constants
#define N_B   4
#define C_IN  256
#define H_IM  64
#define W_IM  64
#define OC    256
#define K2    9
#define OMC   27
#define HW    (H_IM*W_IM)        // 4096
#define NPIX  (N_B*HW)           // 16384
#define KDIM  (C_IN*K2)          // 2304
#define NCHK  (KDIM/32)          // 72
#define NTILE (NPIX/128)         // 128

// ---------------- device scratch ----------------
__device__ float  g_om  [(size_t)N_B * OMC * HW];
__device__ float  g_xt  [(size_t)NPIX * C_IN];          // x transposed: [n][hw][c]
__device__ __half g_colA[(size_t)NTILE * NCHK * 4096];  // tiled im2col, swizzled
__device__ __half g_wtB [(size_t)NCHK * 8192];          // dcn weights, pre-swizzled
__device__ __half g_owB [(size_t)NCHK * 1024];          // offset weights, pre-swizzled

__device__ __host__ __forceinline__ uint32_t swz64(uint32_t a) {
    return a ^ (((a >> 7) & 3u) << 4);
}
__device__ __host__ __forceinline__ uint32_t swzA(uint32_t a) {
    return a ^ (((a >> 8) & 7u) << 4);
}

__device__ __forceinline__ void sts16(uint32_t addr, unsigned short v) {
    asm volatile("st.shared.u16 [%0], %1;" :: "r"(addr), "h"(v));
}
__device__ __forceinline__ uint32_t lds32(uint32_t addr) {
    uint32_t v;
    asm volatile("ld.shared.b32 %0, [%1];" : "=r"(v) : "r"(addr));
    return v;
}
__device__ __forceinline__ void ldmx4(uint32_t* r, uint32_t addr) {
    asm volatile("ldmatrix.sync.aligned.m8n8.x4.shared.b16 {%0,%1,%2,%3}, [%4];"
        : "=r"(r[0]), "=r"(r[1]), "=r"(r[2]), "=r"(r[3]) : "r"(addr));
}
__device__ __forceinline__ void ldmx4t(uint32_t* r, uint32_t addr) {
    asm volatile("ldmatrix.sync.aligned.m8n8.x4.trans.shared.b16 {%0,%1,%2,%3}, [%4];"
        : "=r"(r[0]), "=r"(r[1]), "=r"(r[2]), "=r"(r[3]) : "r"(addr));
}
__device__ __forceinline__ void mma_f16(float* c, const uint32_t* a, const uint32_t* b) {
    asm volatile(
        "mma.sync.aligned.m16n8k16.row.col.f32.f16.f16.f32 "
        "{%0,%1,%2,%3}, {%4,%5,%6,%7}, {%8,%9}, {%0,%1,%2,%3};"
        : "+f"(c[0]), "+f"(c[1]), "+f"(c[2]), "+f"(c[3])
        : "r"(a[0]), "r"(a[1]), "r"(a[2]), "r"(a[3]), "r"(b[0]), "r"(b[1]));
}

// ---------------------------------------------------------------------------
// Prep: pack both weight tensors (fp16, chunk-major, pre-swizzled).
// ---------------------------------------------------------------------------
__global__ void prep_kernel(const float* __restrict__ dw,
                            const float* __restrict__ ow)
{
    if (blockIdx.x < 256) {
        int oc = blockIdx.x;
        int c  = threadIdx.x;
        #pragma unroll
        for (int k = 0; k < 9; k++) {
            float w = dw[((size_t)oc * C_IN + c) * K2 + k];
            int ch  = k * 8 + (c >> 5);
            int kcl = c & 31;
            uint32_t raw = (uint32_t)oc * 64 + kcl * 2;
            g_wtB[(size_t)ch * 8192 + (swz64(raw) >> 1)] = __float2half_rn(w);
        }
    } else {
        int ch = blockIdx.x - 256;
        int k  = ch >> 3;
        int c0 = (ch & 7) * 32;
        #pragma unroll
        for (int it = 0; it < 4; it++) {
            int idx = threadIdx.x + it * 256;
            int oc = idx >> 5, kcl = idx & 31;
            float w = (oc < OMC)
                ? ow[((size_t)oc * C_IN + c0 + kcl) * K2 + k] : 0.f;
            uint32_t raw = (uint32_t)oc * 64 + kcl * 2;
            g_owB[(size_t)ch * 1024 + (swz64(raw) >> 1)] = __float2half_rn(w);
        }
    }
}

// ---------------------------------------------------------------------------
// Transpose x [n][c][hw] -> g_xt [n][hw][c].
// ---------------------------------------------------------------------------
__global__ void transpose_x_kernel(const float* __restrict__ x)
{
    __shared__ float ts[64][65];
    const int hw0 = blockIdx.x * 64, c0 = blockIdx.y * 64, n = blockIdx.z;
    const float* xn = x + ((size_t)(n * C_IN + c0) << 12) + hw0;
    for (int i = threadIdx.x; i < 64 * 64; i += 256) {
        int r = i >> 6, col = i & 63;
        ts[r][col] = xn[((size_t)r << 12) + col];
    }
    __syncthreads();
    float* xtn = g_xt + (((size_t)n << 12) + hw0) * C_IN + c0;
    for (int i = threadIdx.x; i < 64 * 64; i += 256) {
        int r = i >> 6, col = i & 63;
        xtn[(size_t)r * C_IN + col] = ts[col][r];
    }
}

// ---------------------------------------------------------------------------
// Offset conv as fp16 implicit GEMM (unchanged from R8)
// ---------------------------------------------------------------------------
#define CV_APITCH 272
#define CV_A_SZ   (32 * CV_APITCH)
#define CV_B_SZ   2048
#define CV_STG    (CV_A_SZ + CV_B_SZ)

__global__ void __launch_bounds__(256, 1) conv_gemm_kernel(
    const float* __restrict__ x, const float* __restrict__ ob)
{
    __shared__ char sm[2 * CV_STG];
    const uint32_t sb = (uint32_t)__cvta_generic_to_shared(sm);
    const int tid = threadIdx.x;
    const int wid = tid >> 5, lid = tid & 31;
    const int bm0 = blockIdx.x * 128;
    const int nIdx = bm0 >> 12, hwb = bm0 & 4095, ho0 = hwb >> 6;
    const float* xn = x + ((size_t)nIdx * C_IN << 12);

    const int p = tid & 127;
    const int kcl0 = tid >> 7;
    const int pho = p >> 6, pwo = p & 63;

    float acc[4][4];
    #pragma unroll
    for (int j = 0; j < 4; j++)
        #pragma unroll
        for (int q = 0; q < 4; q++) acc[j][q] = 0.f;

    auto build = [&](int ch, int st) {
        const int k = ch >> 3, c0 = (ch & 7) * 32;
        const int dy = k / 3 - 1, dx = k % 3 - 1;
        const int hy = ho0 + pho + dy;
        const int wx = pwo + dx;
        const bool v = ((unsigned)hy < 64u) && ((unsigned)wx < 64u);
        const float* src = xn + ((size_t)(c0 + kcl0) << 12) + (hy << 6) + wx;
        const uint32_t dst = sb + st * CV_STG + kcl0 * CV_APITCH + p * 2;
        #pragma unroll
        for (int it = 0; it < 16; it++) {
            float val = 0.f;
            if (v) val = src[(size_t)(it * 2) << 12];
            sts16(dst + it * 2 * CV_APITCH,
                  __half_as_ushort(__float2half_rn(val)));
        }
        if (tid < 128) {
            const uint4* bsrc = (const uint4*)(g_owB + (size_t)ch * 1024);
            *(uint4*)(sm + st * CV_STG + CV_A_SZ + tid * 16) = bsrc[tid];
        }
    };

    const int qq = lid >> 3, jr = lid & 7;
    const uint32_t aoff = (uint32_t)(((qq >> 1) * 8 + jr) * CV_APITCH
                                     + (wid * 16 + (qq & 1) * 8) * 2);
    const int oc_l = (qq >> 1) * 8 + jr;

    build(0, 0);
    __syncthreads();

    for (int ch = 0; ch < NCHK; ch++) {
        const int st = ch & 1;
        if (ch + 1 < NCHK) build(ch + 1, st ^ 1);

        const uint32_t ab = sb + st * CV_STG;
        const uint32_t bb = ab + CV_A_SZ;
        #pragma unroll
        for (int kp = 0; kp < 2; kp++) {
            uint32_t Af[4];
            ldmx4t(Af, ab + aoff + kp * (16 * CV_APITCH));
            #pragma unroll
            for (int pi = 0; pi < 2; pi++) {
                uint32_t Bf[4];
                uint32_t raw = (uint32_t)(oc_l + pi * 16) * 64
                             + (kp * 2 + (qq & 1)) * 16;
                ldmx4(Bf, bb + swz64(raw));
                mma_f16(acc[pi*2],   Af, &Bf[0]);
                mma_f16(acc[pi*2+1], Af, &Bf[2]);
            }
        }
        __syncthreads();
    }

    float* T = (float*)sm;
    const int r0 = wid * 16 + (lid >> 2);
    #pragma unroll
    for (int jj = 0; jj < 4; jj++) {
        int oc = jj * 8 + (lid & 3) * 2;
        T[ oc      * 136 + r0    ] = acc[jj][0];
        T[(oc + 1) * 136 + r0    ] = acc[jj][1];
        T[ oc      * 136 + r0 + 8] = acc[jj][2];
        T[(oc + 1) * 136 + r0 + 8] = acc[jj][3];
    }
    __syncthreads();
    for (int idx = tid; idx < OMC * 128; idx += 256) {
        int o = idx >> 7, m = idx & 127;
        g_om[((size_t)(nIdx * OMC + o) << 12) + hwb + m] = T[o * 136 + m] + ob[o];
    }
}

// ---------------------------------------------------------------------------
// Sampling v3: channel-major gathers, grid (128 tiles x 9 taps), 256 threads.
// Warp = one 32-channel group; two 64-px halves per warp. ~38KB static smem.
// ---------------------------------------------------------------------------
__global__ void __launch_bounds__(256, 5) sample3_kernel()
{
    __shared__ float4 sW[128];
    __shared__ int4   sI[128];
    __shared__ char   stg[8 * 4224];     // per-warp [32 ch][66 halfs], pitch 132B

    const int tile = blockIdx.x;
    const int k    = blockIdx.y;         // tap 0..8
    const int n    = tile >> 5;
    const int hw0  = (tile & 31) * 128;
    const int tid  = threadIdx.x;

    // ---- phase 1: bilinear weights + channel-major corner offsets (this tap)
    const float* omn = g_om + (size_t)n * OMC * HW;
    if (tid < 128) {
        int pl = tid;
        int p = hw0 + pl;
        int ho = p >> 6, wo = p & 63;

        float oy = omn[((size_t)(2*k    ) << 12) + p];
        float ox = omn[((size_t)(2*k + 1) << 12) + p];
        float mv = omn[((size_t)(18 + k ) << 12) + p];
        float m  = 1.0f / (1.0f + expf(-mv));

        float him = (float)(ho + (k / 3) - 1) + oy;
        float wim = (float)(wo + (k % 3) - 1) + ox;

        float y0 = floorf(him), x0 = floorf(wim);
        float lh = him - y0,    lw = wim - x0;
        float hh = 1.0f - lh,   hw = 1.0f - lw;
        float y1 = y0 + 1.0f,   x1 = x0 + 1.0f;

        float vy0 = (y0 >= 0.f && y0 <= 63.f) ? 1.f : 0.f;
        float vy1 = (y1 >= 0.f && y1 <= 63.f) ? 1.f : 0.f;
        float vx0 = (x0 >= 0.f && x0 <= 63.f) ? 1.f : 0.f;
        float vx1 = (x1 >= 0.f && x1 <= 63.f) ? 1.f : 0.f;

        int iy0 = (int)fminf(fmaxf(y0, 0.f), 63.f);
        int iy1 = (int)fminf(fmaxf(y1, 0.f), 63.f);
        int ix0 = (int)fminf(fmaxf(x0, 0.f), 63.f);
        int ix1 = (int)fminf(fmaxf(x1, 0.f), 63.f);

        sW[pl] = make_float4(hh*hw*m*vy0*vx0, hh*lw*m*vy0*vx1,
                             lh*hw*m*vy1*vx0, lh*lw*m*vy1*vx1);
        sI[pl] = make_int4((iy0*64 + ix0) << 8, (iy0*64 + ix1) << 8,
                           (iy1*64 + ix0) << 8, (iy1*64 + ix1) << 8);
    }
    __syncthreads();

    // ---- phase 2: warp g gathers 32 channels x 128 px (two 64-px halves)
    const int wid = tid >> 5, lid = tid & 31;
    const int g = wid;                                  // channel group 0..7
    const float* xc = g_xt + ((size_t)n << 12) * C_IN + g * 32 + lid;
    char* cb = (char*)g_colA + (size_t)tile * NCHK * 8192
             + (size_t)(k * 8 + g) * 8192;
    const uint32_t stgb = (uint32_t)__cvta_generic_to_shared(stg) + wid * 4224;

    #pragma unroll
    for (int pb = 0; pb < 2; pb++) {
        #pragma unroll 4
        for (int j = 0; j < 64; j++) {
            int t = (pb << 6) + j;
            float4 w = sW[t];
            int4   I = sI[t];
            float v = w.x * xc[I.x] + w.y * xc[I.y]
                    + w.z * xc[I.z] + w.w * xc[I.w];
            sts16(stgb + lid * 132 + j * 2,
                  __half_as_ushort(__float2half_rn(v)));
        }
        __syncwarp();
        #pragma unroll
        for (int kcl = 0; kcl < 32; kcl++) {
            uint32_t v = lds32(stgb + kcl * 132 + lid * 4);
            *(uint32_t*)(cb + swzA((uint32_t)(kcl * 256 + pb * 128 + lid * 4))) = v;
        }
        __syncwarp();
    }
}

// ---------------------------------------------------------------------------
// fp16 mma GEMM: contiguous bulk staging, 4 stages (unchanged from R8)
// ---------------------------------------------------------------------------
#define A_TILE   8192
#define B_TILE   16384
#define STAGE_SZ (A_TILE + B_TILE)
#define NSTAGE   4
#define MBAR_OFF (NSTAGE * STAGE_SZ)
#define GEMM_SMEM (MBAR_OFF + 128)
#define STAGE_BYTES STAGE_SZ

__device__ __forceinline__ void bulk_g2s(uint32_t dst, const void* src,
                                         uint32_t bytes, uint32_t mbar) {
    asm volatile(
        "cp.async.bulk.shared::cluster.global.mbarrier::complete_tx::bytes "
        "[%0], [%1], %2, [%3];"
        :: "r"(dst), "l"(src), "r"(bytes), "r"(mbar) : "memory");
}
__device__ __forceinline__ void mbar_init(uint32_t a, uint32_t c) {
    asm volatile("mbarrier.init.shared.b64 [%0], %1;" :: "r"(a), "r"(c) : "memory");
}
__device__ __forceinline__ void mbar_expect(uint32_t a, uint32_t b) {
    asm volatile("mbarrier.arrive.expect_tx.shared.b64 _, [%0], %1;" :: "r"(a), "r"(b) : "memory");
}
__device__ __forceinline__ void mbar_arrive(uint32_t a) {
    asm volatile("mbarrier.arrive.shared.b64 _, [%0];" :: "r"(a) : "memory");
}
__device__ __forceinline__ void mbar_wait(uint32_t mbar, uint32_t parity) {
    uint32_t done;
    asm volatile("{\n\t.reg .pred p;\n\t"
        "mbarrier.try_wait.parity.acquire.cta.shared::cta.b64 p, [%1], %2;\n\t"
        "selp.b32 %0, 1, 0, p;\n\t}"
        : "=r"(done) : "r"(mbar), "r"(parity) : "memory");
    if (!done) {
        asm volatile("{\n\t.reg .pred P1;\n\t"
            "W_%=:\n\t"
            "mbarrier.try_wait.parity.acquire.cta.shared::cta.b64 P1, [%0], %1, 0x989680;\n\t"
            "@P1 bra.uni D_%=;\n\t"
            "bra.uni W_%=;\n\t"
            "D_%=:\n\t}" :: "r"(mbar), "r"(parity) : "memory");
    }
}

__global__ void __launch_bounds__(512, 1) gemm_bulk_kernel(float* __restrict__ out)
{
    extern __shared__ char sm[];
    const uint32_t sb = (uint32_t)__cvta_generic_to_shared(sm);
    const int tid = threadIdx.x;
    const int wid = tid >> 5, lid = tid & 31;
    const int warpM = wid & 3, warpN = wid >> 2;
    const int bm0 = blockIdx.x * 128;
    const int tile = blockIdx.x;

    if (tid == 0) {
        #pragma unroll
        for (int s = 0; s < NSTAGE; s++) {
            mbar_init(sb + MBAR_OFF + s*16, 1);
            mbar_init(sb + MBAR_OFF + s*16 + 8, 512);
        }
    }
    __syncthreads();

    float acc[2][8][4];
    #pragma unroll
    for (int i = 0; i < 2; i++)
        #pragma unroll
        for (int j = 0; j < 8; j++)
            #pragma unroll
            for (int q = 0; q < 4; q++) acc[i][j][q] = 0.f;

    const char* aSrc = (const char*)g_colA + (size_t)tile * NCHK * 8192;

    auto fill = [&](int f) {
        int s = f % NSTAGE;
        uint32_t base = sb + s * STAGE_SZ;
        uint32_t mb   = sb + MBAR_OFF + s * 16;
        mbar_expect(mb, STAGE_BYTES);
        bulk_g2s(base, aSrc + (size_t)f * 8192, A_TILE, mb);
        bulk_g2s(base + A_TILE, g_wtB + (size_t)f * 8192, B_TILE, mb);
    };

    if (tid == 0) {
        #pragma unroll
        for (int f = 0; f < NSTAGE - 1; f++) fill(f);
    }

    const int qq = lid >> 3;
    const int jr = lid & 7;
    const uint32_t aoff = (uint32_t)(((qq >> 1) * 8 + jr) * 256
                                     + (warpM * 32 + (qq & 1) * 8) * 2);
    const int oc_lane = warpN * 64 + (qq >> 1) * 8 + jr;

    for (int ch = 0; ch < NCHK; ch++) {
        if (tid == 0) {
            int f = ch + NSTAGE - 1;
            if (f < NCHK) {
                if (f >= NSTAGE)
                    mbar_wait(sb + MBAR_OFF + (f % NSTAGE) * 16 + 8,
                              ((f / NSTAGE) - 1) & 1);
                fill(f);
            }
        }
        const int s = ch % NSTAGE;
        mbar_wait(sb + MBAR_OFF + s * 16, (ch / NSTAGE) & 1);

        const uint32_t ab = sb + s * STAGE_SZ;
        const uint32_t bb = ab + A_TILE;

        #pragma unroll
        for (int kp = 0; kp < 2; kp++) {
            uint32_t Af[2][4], Bf[4][4];
            #pragma unroll
            for (int mi = 0; mi < 2; mi++)
                ldmx4t(Af[mi], ab + swzA(aoff + kp * (16 * 256) + mi * 32));
            #pragma unroll
            for (int pi = 0; pi < 4; pi++) {
                uint32_t raw = (uint32_t)(oc_lane + pi * 16) * 64
                             + (kp * 2 + (qq & 1)) * 16;
                ldmx4(Bf[pi], bb + swz64(raw));
            }
            #pragma unroll
            for (int mi = 0; mi < 2; mi++)
                #pragma unroll
                for (int pi = 0; pi < 4; pi++) {
                    mma_f16(acc[mi][pi*2],   Af[mi], &Bf[pi][0]);
                    mma_f16(acc[mi][pi*2+1], Af[mi], &Bf[pi][2]);
                }
        }
        mbar_arrive(sb + MBAR_OFF + s * 16 + 8);
    }

    const int nIdx = bm0 >> 12;
    const int hwb  = bm0 & 4095;
    #pragma unroll
    for (int mi = 0; mi < 2; mi++) {
        int r = hwb + warpM * 32 + mi * 16 + (lid >> 2);
        #pragma unroll
        for (int jj = 0; jj < 8; jj++) {
            int oc = warpN * 64 + jj * 8 + (lid & 3) * 2;
            size_t base = ((size_t)(nIdx * OC + oc) << 12);
            out[base + r]            = acc[mi][jj][0];
            out[base + 4096 + r]     = acc[mi][jj][1];
            out[base + r + 8]        = acc[mi][jj][2];
            out[base + 4096 + r + 8] = acc[mi][jj][3];
        }
    }
}

// ---------------------------------------------------------------------------
extern "C" void kernel_launch(void* const* d_in, const int* in_sizes, int n_in,
                              void* d_out, int out_size)
{
    const float* x  = (const float*)d_in[0];
    const float* ow = (const float*)d_in[1];
    const float* ob = (const float*)d_in[2];
    const float* dw = (const float*)d_in[3];
    float* out = (float*)d_out;

    cudaFuncSetAttribute(gemm_bulk_kernel,
        cudaFuncAttributeMaxDynamicSharedMemorySize, GEMM_SMEM);

    prep_kernel<<<256 + NCHK, 256>>>(dw, ow);
    transpose_x_kernel<<<dim3(64, 4, 4), 256>>>(x);
    conv_gemm_kernel<<<NPIX/128, 256>>>(x, ob);
    sample3_kernel<<<dim3(NTILE, 9), 256>>>();
    gemm_bulk_kernel<<<NPIX/128, 512, GEMM_SMEM>>>(out);
}